// round 4
// baseline (speedup 1.0000x reference)
#include <cuda_runtime.h>

// MaxFeatBlockDescriptorLayer, fused single launch:
//   Phase 1 (all 128 blocks): coalesced chunk reduction of prob [B,16384,8]
//     -> per-chunk (packed max|~idx, sum) partials per (b,k). Fixed slots.
//   Grid barrier (spin on atomic counter; 128 blocks = 1 wave, safe).
//   Phase 2 (blocks 0..B*8-1): reduce 64 partials, gather emb[b,argmax,:]*mask.
//
// argmax tie-break = first index, via packing (bits(v)<<32)|(N-1-n) and max
// (prob >= 0 so float bits are order-monotonic).
//
// R3 fix: ALL shared memory declared at kernel scope; sv explicitly 16B
// aligned (R2's scoped smem overlay broke float4 alignment -> trap).

#define N_POS    16384
#define N_CLS    8
#define C_DIM    2048
#define TAU      0.3f
#define CHUNKS   64
#define POS_PC   (N_POS / CHUNKS)        // 256
#define NTHREADS 256
#define MAX_B    8

__device__ unsigned long long g_pack[MAX_B * N_CLS * CHUNKS];
__device__ float              g_sum [MAX_B * N_CLS * CHUNKS];
__device__ unsigned int       g_arrive;
__device__ unsigned int       g_done;

__global__ __launch_bounds__(NTHREADS)
void mfbd_fused(const float* __restrict__ emb,
                const float* __restrict__ prob,
                float* __restrict__ out,
                int nblocks, int B)
{
    const int t = threadIdx.x;

    // All smem at kernel scope, no overlays, explicit 16B alignment.
    __shared__ __align__(16) float sv[POS_PC * N_CLS];   // 8 KB
    __shared__ unsigned long long sp[CHUNKS];
    __shared__ float ss[CHUNKS];
    __shared__ int   s_arg;
    __shared__ float s_mask;

    // ---------------- Phase 1: chunk reduction ----------------
    {
        const int b     = blockIdx.x / CHUNKS;
        const int chunk = blockIdx.x % CHUNKS;

        const float4* __restrict__ p4 =
            (const float4*)prob + ((size_t)b * N_POS + (size_t)chunk * POS_PC) * 2;

        float4 a0 = __ldg(p4 + t);
        float4 a1 = __ldg(p4 + t + NTHREADS);
        ((float4*)sv)[t]            = a0;
        ((float4*)sv)[t + NTHREADS] = a1;
        __syncthreads();

        const int w    = t >> 5;    // warp = class
        const int lane = t & 31;

        unsigned long long best = 0ULL;
        float s = 0.0f;

        #pragma unroll
        for (int i = 0; i < POS_PC / 32; ++i) {
            const int p = lane + i * 32;
            const float v = sv[p * N_CLS + w];
            s += v;
            const unsigned comp = (unsigned)(N_POS - 1 - (chunk * POS_PC + p));
            const unsigned long long pk =
                ((unsigned long long)__float_as_uint(v) << 32) | comp;
            best = best > pk ? best : pk;
        }

        #pragma unroll
        for (int off = 16; off > 0; off >>= 1) {
            const unsigned long long ob = __shfl_down_sync(0xffffffffu, best, off);
            best = best > ob ? best : ob;
            s += __shfl_down_sync(0xffffffffu, s, off);
        }

        if (lane == 0) {
            const int slot = (b * N_CLS + w) * CHUNKS + chunk;
            g_pack[slot] = best;
            g_sum[slot]  = s;
        }
        __syncthreads();          // all partial writes issued block-wide
    }

    // ---------------- Grid barrier arrive ----------------
    if (t == 0) {
        __threadfence();                    // make partials visible
        atomicAdd(&g_arrive, 1u);
    }

    const int ngather = B * N_CLS;          // 16
    if (blockIdx.x >= ngather) return;      // non-gather blocks done

    // ---------------- Spin until all arrived ----------------
    if (t == 0) {
        while (atomicAdd(&g_arrive, 0u) < (unsigned)nblocks) { }
        __threadfence();                    // acquire partials
    }
    __syncthreads();

    // ---------------- Phase 2: final reduce + gather ----------------
    const int b = blockIdx.x / N_CLS;
    const int k = blockIdx.x % N_CLS;

    const int base = (b * N_CLS + k) * CHUNKS;
    if (t < CHUNKS) {
        sp[t] = g_pack[base + t];
        ss[t] = g_sum[base + t];
    }
    __syncthreads();

    if (t < 32) {
        unsigned long long bp = sp[t] > sp[t + 32] ? sp[t] : sp[t + 32];
        float s = ss[t] + ss[t + 32];
        #pragma unroll
        for (int off = 16; off > 0; off >>= 1) {
            const unsigned long long ob = __shfl_down_sync(0xffffffffu, bp, off);
            bp = bp > ob ? bp : ob;
            s += __shfl_down_sync(0xffffffffu, s, off);
        }
        if (t == 0) {
            s_arg  = N_POS - 1 - (int)(unsigned)(bp & 0xffffffffu);
            s_mask = (s * (1.0f / N_POS) > TAU) ? 1.0f : 0.0f;
        }
    }
    __syncthreads();

    const float4* __restrict__ src =
        (const float4*)(emb + ((size_t)b * N_POS + (size_t)s_arg) * C_DIM);
    float4* __restrict__ dst =
        (float4*)(out + ((size_t)b * N_CLS + (size_t)k) * C_DIM);

    const float m = s_mask;
    // 512 float4 total, 256 threads x 2 independent loads
    float4 v0 = __ldg(src + t);
    float4 v1 = __ldg(src + t + NTHREADS);
    v0.x *= m; v0.y *= m; v0.z *= m; v0.w *= m;
    v1.x *= m; v1.y *= m; v1.z *= m; v1.w *= m;
    dst[t]            = v0;
    dst[t + NTHREADS] = v1;

    // ---------------- Replay-safe counter reset ----------------
    __syncthreads();
    if (t == 0) {
        const unsigned d = atomicAdd(&g_done, 1u);
        if (d == (unsigned)(ngather - 1)) {   // all spinners have passed
            g_arrive = 0u;
            g_done   = 0u;
            __threadfence();
        }
    }
}

extern "C" void kernel_launch(void* const* d_in, const int* in_sizes, int n_in,
                              void* d_out, int out_size)
{
    const float* emb  = (const float*)d_in[0];
    const float* prob = (const float*)d_in[1];
    float* out = (float*)d_out;

    const int B = in_sizes[0] / (N_POS * C_DIM);   // = 2
    const int nblocks = B * CHUNKS;                // 128 <= 148 SMs: one wave

    mfbd_fused<<<nblocks, NTHREADS>>>(emb, prob, out, nblocks, B);
}